// round 8
// baseline (speedup 1.0000x reference)
#include <cuda_runtime.h>
#include <cuda_fp16.h>

// CustomAttention: out[b,n] = b0 * sum_m tanh(a0*x[b,n]*x[b,m]) * x[b,m]
// B=16, N=4096. Symmetric 256x256 tiling at the MUFU result roofline.
// R7b: single kernel; reduction fused via last-block-arrives counters
// (16th block feeding an output tile reduces it, fixed slot order ->
// deterministic). Release fence before arrival, ACQUIRE fence after the
// last-arrival observation (fixed vs R7). Scratch stays L2-resident.

#define NBATCH 16
#define NDIM   4096
#define TILE   256
#define NTILE  (NDIM / TILE)              // 16
#define NOFF   (NTILE * (NTILE - 1) / 2)  // 120
#define NPAIR  (NOFF + NTILE)             // 136
#define BT     256

__device__ __half g_scratch[NBATCH][NTILE][NDIM];   // 2 MB, exclusive-write
__device__ int    g_arrive[NBATCH][NTILE];          // zero-init; self-resetting

__device__ __forceinline__ __half2 tanh2(__half2 v) {
    unsigned u = *reinterpret_cast<unsigned*>(&v);
    unsigned r;
    asm("tanh.approx.f16x2 %0, %1;" : "=r"(r) : "r"(u));
    return *reinterpret_cast<__half2*>(&r);
}
__device__ __forceinline__ unsigned h2u(__half2 v) { return *reinterpret_cast<unsigned*>(&v); }
__device__ __forceinline__ __half2 u2h(unsigned v) { return *reinterpret_cast<__half2*>(&v); }

// Reduce output tile R for this batch: 256 threads, one row each.
__device__ __forceinline__ void reduce_tile(int batch, int R, float b0,
                                            float* __restrict__ out, int tid)
{
    const int n = R * TILE + tid;
    float s = 0.f;
    #pragma unroll
    for (int slot = 0; slot < NTILE; ++slot)
        s += __half2float(g_scratch[batch][slot][n]);
    out[batch * NDIM + n] = b0 * s;
}

__global__ __launch_bounds__(BT)
void sym_tile_kernel(const float* __restrict__ x,
                     const float* __restrict__ a,
                     const float* __restrict__ bco,
                     float* __restrict__ out)
{
    __shared__ __half2 xhJd[4][64];            // replicated col tile, 2 KB
    __shared__ float2  colred[8][TILE / 2];    // 8 KB
    __shared__ int     s_arr[2];               // arrival ranks for tiles I, J

    const int batch = blockIdx.y;
    const int tid   = threadIdx.x;
    const int w     = tid >> 5;
    const int L     = tid & 31;

    // bid 0..119: off-diagonal pairs I<J; bid 120..135: diagonal (light, last)
    int I, J;
    if (blockIdx.x < NOFF) {
        int q = blockIdx.x, i = 0;
        while (true) { int cnt = NTILE - 1 - i; if (q < cnt) break; q -= cnt; i++; }
        I = i; J = i + 1 + q;
    } else {
        I = J = blockIdx.x - NOFF;
    }

    const float* __restrict__ xb = x + batch * NDIM;

    // Fill replicated col tile: 4 rb x 64 entries
    {
        const int rb = tid >> 6;
        const int j  = tid & 63;
        const int pr = rb * 32 + (j & 31);
        float2 v = reinterpret_cast<const float2*>(xb + J * TILE)[pr];
        xhJd[rb][j] = __floats2half2_rn(v.x, v.y);
    }

    const float xn = xb[I * TILE + tid];
    const __half2 ch  = __float2half2_rn(a[0] * xn);
    const __half2 xi2 = __float2half2_rn(xn);
    __syncthreads();

    float row_f = 0.f;

    if (I == J) {
        #pragma unroll 1
        for (int rb = 0; rb < 4; ++rb) {
            __half2 racc = __float2half2_rn(0.f);
            #pragma unroll
            for (int k = 0; k < 32; ++k) {
                __half2 h = xhJd[rb][k];
                racc = __hfma2(tanh2(__hmul2(ch, h)), h, racc);
            }
            float2 f = __half22float2(racc);
            row_f += f.x + f.y;
        }
        g_scratch[batch][I][I * TILE + tid] = __float2half(row_f);
    } else {
        #pragma unroll 1
        for (int rb = 0; rb < 4; ++rb) {
            __half2 racc = __float2half2_rn(0.f);
            __half2 cacc = __float2half2_rn(0.f);
            #pragma unroll
            for (int k = 0; k < 32; ++k) {
                __half2 h = xhJd[rb][L + k];             // affine LDS
                __half2 t = tanh2(__hmul2(ch, h));
                racc = __hfma2(t, h, racc);              // rows of I
                unsigned v2 = h2u(__hmul2(t, xi2));      // t*x_row -> rows of J
                unsigned rv = __shfl_sync(0xffffffffu, v2, L + 32 - k);
                cacc = __hadd2(cacc, u2h(rv));
            }
            float2 f = __half22float2(racc);
            row_f += f.x + f.y;
            colred[w][rb * 32 + L] = __half22float2(cacc);
        }
        __syncthreads();

        float s = 0.f;
        #pragma unroll
        for (int w2 = 0; w2 < 8; ++w2) {
            float2 f = colred[w2][tid >> 1];
            s += (tid & 1) ? f.y : f.x;
        }
        g_scratch[batch][J][I * TILE + tid] = __float2half(row_f); // rows I, slot J
        g_scratch[batch][I][J * TILE + tid] = __float2half(s);     // rows J, slot I
    }

    // ---- last-block-arrives fused reduction ----
    __threadfence();            // RELEASE: scratch writes visible before arrival
    __syncthreads();            // all threads' stores issued before the atomic
    if (tid == 0) {
        s_arr[0] = atomicAdd(&g_arrive[batch][I], 1);
        s_arr[1] = (I != J) ? atomicAdd(&g_arrive[batch][J], 1) : -1;
    }
    __syncthreads();

    const bool redI = (s_arr[0] == NTILE - 1);
    const bool redJ = (s_arr[1] == NTILE - 1);
    if (redI || redJ)
        __threadfence();        // ACQUIRE: order counter observation before scratch reads

    const float b0 = bco[0];
    if (redI) {                 // 16th arrival for tile I
        reduce_tile(batch, I, b0, out, tid);
        __syncthreads();
        if (tid == 0) atomicExch(&g_arrive[batch][I], 0);   // reset for replay
    }
    if (redJ) {                 // 16th arrival for tile J
        reduce_tile(batch, J, b0, out, tid);
        __syncthreads();
        if (tid == 0) atomicExch(&g_arrive[batch][J], 0);
    }
}

extern "C" void kernel_launch(void* const* d_in, const int* in_sizes, int n_in,
                              void* d_out, int out_size)
{
    const float* x = (const float*)d_in[0];
    const float* a = (const float*)d_in[1];
    const float* b = (const float*)d_in[2];
    float* out = (float*)d_out;

    dim3 grid(NPAIR, NBATCH);               // 136 x 16 = 2176 blocks
    sym_tile_kernel<<<grid, BT>>>(x, a, b, out);
}

// round 9
// speedup vs baseline: 1.0625x; 1.0625x over previous
#include <cuda_runtime.h>
#include <cuda_fp16.h>

// CustomAttention: out[b,n] = b0 * sum_m tanh(a0*x[b,n]*x[b,m]) * x[b,m]
// B=16, N=4096. Symmetric 256x256 tiling at the MUFU result roofline.
// R9: fused last-block-arrives reduction WITHOUT __threadfence.
// sm_100a L1 is write-through -> scratch STGs are at L2 on retire;
// release-atomic arrival (atom.add.release.gpu) orders them with no
// MEMBAR/CCTL.IVALL (the R8 regression: per-block L1D flushes stalled
// the co-resident blocks' LDS streams). Readers use __ldcg (L2-only).

#define NBATCH 16
#define NDIM   4096
#define TILE   256
#define NTILE  (NDIM / TILE)              // 16
#define NOFF   (NTILE * (NTILE - 1) / 2)  // 120
#define NPAIR  (NOFF + NTILE)             // 136
#define BT     256

__device__ __half g_scratch[NBATCH][NTILE][NDIM];   // 2 MB, exclusive-write
__device__ int    g_arrive[NBATCH][NTILE];          // zero-init; self-resetting

__device__ __forceinline__ __half2 tanh2(__half2 v) {
    unsigned u = *reinterpret_cast<unsigned*>(&v);
    unsigned r;
    asm("tanh.approx.f16x2 %0, %1;" : "=r"(r) : "r"(u));
    return *reinterpret_cast<__half2*>(&r);
}
__device__ __forceinline__ unsigned h2u(__half2 v) { return *reinterpret_cast<unsigned*>(&v); }
__device__ __forceinline__ __half2 u2h(unsigned v) { return *reinterpret_cast<__half2*>(&v); }

// Release-ordered arrival: returns previous count. No L1 flush.
__device__ __forceinline__ int arrive_release(int* ctr) {
    int old;
    asm volatile("atom.add.release.gpu.global.s32 %0, [%1], 1;"
                 : "=r"(old) : "l"(ctr) : "memory");
    return old;
}

// Reduce output tile R: 256 threads, one row each; L2-only reads.
__device__ __forceinline__ void reduce_tile(int batch, int R, float b0,
                                            float* __restrict__ out, int tid)
{
    const int n = R * TILE + tid;
    float s = 0.f;
    #pragma unroll
    for (int slot = 0; slot < NTILE; ++slot)
        s += __half2float(__ldcg(&g_scratch[batch][slot][n]));
    out[batch * NDIM + n] = b0 * s;
}

__global__ __launch_bounds__(BT)
void sym_tile_kernel(const float* __restrict__ x,
                     const float* __restrict__ a,
                     const float* __restrict__ bco,
                     float* __restrict__ out)
{
    __shared__ __half2 xhJd[4][64];            // replicated col tile, 2 KB
    __shared__ float2  colred[8][TILE / 2];    // 8 KB
    __shared__ int     s_arr[2];               // arrival ranks for tiles I, J

    const int batch = blockIdx.y;
    const int tid   = threadIdx.x;
    const int w     = tid >> 5;
    const int L     = tid & 31;

    // bid 0..119: off-diagonal pairs I<J; bid 120..135: diagonal (light, last)
    int I, J;
    if (blockIdx.x < NOFF) {
        int q = blockIdx.x, i = 0;
        while (true) { int cnt = NTILE - 1 - i; if (q < cnt) break; q -= cnt; i++; }
        I = i; J = i + 1 + q;
    } else {
        I = J = blockIdx.x - NOFF;
    }

    const float* __restrict__ xb = x + batch * NDIM;

    // Fill replicated col tile: 4 rb x 64 entries
    {
        const int rb = tid >> 6;
        const int j  = tid & 63;
        const int pr = rb * 32 + (j & 31);
        float2 v = reinterpret_cast<const float2*>(xb + J * TILE)[pr];
        xhJd[rb][j] = __floats2half2_rn(v.x, v.y);
    }

    const float xn = xb[I * TILE + tid];
    const __half2 ch  = __float2half2_rn(a[0] * xn);
    const __half2 xi2 = __float2half2_rn(xn);
    __syncthreads();

    float row_f = 0.f;

    if (I == J) {
        #pragma unroll 1
        for (int rb = 0; rb < 4; ++rb) {
            __half2 racc = __float2half2_rn(0.f);
            #pragma unroll
            for (int k = 0; k < 32; ++k) {
                __half2 h = xhJd[rb][k];
                racc = __hfma2(tanh2(__hmul2(ch, h)), h, racc);
            }
            float2 f = __half22float2(racc);
            row_f += f.x + f.y;
        }
        g_scratch[batch][I][I * TILE + tid] = __float2half(row_f);
    } else {
        #pragma unroll 1
        for (int rb = 0; rb < 4; ++rb) {
            __half2 racc = __float2half2_rn(0.f);
            __half2 cacc = __float2half2_rn(0.f);
            #pragma unroll
            for (int k = 0; k < 32; ++k) {
                __half2 h = xhJd[rb][L + k];             // affine LDS
                __half2 t = tanh2(__hmul2(ch, h));
                racc = __hfma2(t, h, racc);              // rows of I
                unsigned v2 = h2u(__hmul2(t, xi2));      // t*x_row -> rows of J
                unsigned rv = __shfl_sync(0xffffffffu, v2, L + 32 - k);
                cacc = __hadd2(cacc, u2h(rv));
            }
            float2 f = __half22float2(racc);
            row_f += f.x + f.y;
            colred[w][rb * 32 + L] = __half22float2(cacc);
        }
        __syncthreads();

        float s = 0.f;
        #pragma unroll
        for (int w2 = 0; w2 < 8; ++w2) {
            float2 f = colred[w2][tid >> 1];
            s += (tid & 1) ? f.y : f.x;
        }
        g_scratch[batch][J][I * TILE + tid] = __float2half(row_f); // rows I, slot J
        g_scratch[batch][I][J * TILE + tid] = __float2half(s);     // rows J, slot I
    }

    // ---- last-block-arrives fused reduction (fence-free) ----
    __syncthreads();            // all scratch stores issued (write-through -> L2)
    if (tid == 0) {
        s_arr[0] = arrive_release(&g_arrive[batch][I]);
        s_arr[1] = (I != J) ? arrive_release(&g_arrive[batch][J]) : -1;
    }
    __syncthreads();

    const float b0 = bco[0];
    if (s_arr[0] == NTILE - 1) {            // 16th arrival for tile I
        reduce_tile(batch, I, b0, out, tid);
        __syncthreads();
        if (tid == 0) atomicExch(&g_arrive[batch][I], 0);   // reset for replay
    }
    if (s_arr[1] == NTILE - 1) {            // 16th arrival for tile J
        reduce_tile(batch, J, b0, out, tid);
        __syncthreads();
        if (tid == 0) atomicExch(&g_arrive[batch][J], 0);
    }
}

extern "C" void kernel_launch(void* const* d_in, const int* in_sizes, int n_in,
                              void* d_out, int out_size)
{
    const float* x = (const float*)d_in[0];
    const float* a = (const float*)d_in[1];
    const float* b = (const float*)d_in[2];
    float* out = (float*)d_out;

    dim3 grid(NPAIR, NBATCH);               // 136 x 16 = 2176 blocks
    sym_tile_kernel<<<grid, BT>>>(x, a, b, out);
}